// round 17
// baseline (speedup 1.0000x reference)
#include <cuda_runtime.h>
#include <cuda_bf16.h>

#define B_DIM 128
#define N_DIM 256
#define RSW   148      // P row stride (words): half0 @ +0 (64w), half1 @ +80 (64w)
#define ITERS 50
#define NTHR  512

// ---- smem word offsets ----
#define W_PH   0                       // 37888 : P bf16, split-half rows
#define W_S    37888
#define W_BM   38144
#define W_GA   38400
#define W_U    38656
#define W_VA   38912                   // base % 32 == 0
#define W_VB   39184                   // base % 32 == 16
#define W_SP   39440                   // 4096 : 16 x 256 column partials
#define W_RED  43536                   // 32
#define W_EI   43568                   // 256
#define W_PW   43824                   // 2048 : r^k tables
#define W_AN   45872                   // 8192 : anchor rows
#define SMEM_WORDS (W_AN + 32*256)     // 54064 words = 216256 B

__device__ float    g_sum = 0.f;
__device__ int      g_cnt = 0;
__device__ unsigned g_tk  = 0u;

__device__ __forceinline__ float bf_lo(unsigned w) { return __int_as_float(w << 16); }
__device__ __forceinline__ float bf_hi(unsigned w) { return __int_as_float(w & 0xffff0000u); }

// ------------------------------------------------------------- mega kernel ---
__global__ void __launch_bounds__(NTHR, 1)
mega_kernel(const float* __restrict__ yp, const int* __restrict__ ytr,
            float* __restrict__ out) {
    extern __shared__ unsigned smw[];
    unsigned* Pw = smw + W_PH;
    float* s   = (float*)(smw + W_S);
    float* Bm  = (float*)(smw + W_BM);
    float* gA  = (float*)(smw + W_GA);
    float* u   = (float*)(smw + W_U);
    float* vA  = (float*)(smw + W_VA);
    float* vB  = (float*)(smw + W_VB);
    float* sp  = (float*)(smw + W_SP);
    float* red = (float*)(smw + W_RED);
    int*   ei  = (int*)(smw + W_EI);
    float* pw  = (float*)(smw + W_PW);
    float* AN  = (float*)(smw + W_AN);

    const int tid  = threadIdx.x;
    const int b    = blockIdx.x;
    const int lane = tid & 31;
    const int wid  = tid >> 5;

    // ---- fused global min/max of y_true (L2-hot scan) ----
    int shift;
    {
        const int4* t4 = (const int4*)ytr;
        unsigned umx = 0u, umn = 0u;
        #pragma unroll
        for (int k = 0; k < (B_DIM * N_DIM / 4) / NTHR; k++) {
            int4 x = t4[tid + k * NTHR];
            unsigned a0 = (unsigned)x.x ^ 0x80000000u, a1 = (unsigned)x.y ^ 0x80000000u;
            unsigned a2 = (unsigned)x.z ^ 0x80000000u, a3 = (unsigned)x.w ^ 0x80000000u;
            umx = max(umx, max(max(a0, a1), max(a2, a3)));
            umn = max(umn, max(max(~a0, ~a1), max(~a2, ~a3)));
        }
        for (int o = 16; o; o >>= 1) {
            umx = max(umx, __shfl_xor_sync(0xffffffffu, umx, o));
            umn = max(umn, __shfl_xor_sync(0xffffffffu, umn, o));
        }
        unsigned* ur = (unsigned*)red;
        if (lane == 0) { ur[wid] = umx; ur[16 + wid] = umn; }
        __syncthreads();
        if (tid == 0) {
            for (int k = 1; k < 16; k++) { umx = max(umx, ur[k]); umn = max(umn, ur[16 + k]); }
            red[31] = __int_as_float((int)(umx ^ 0x80000000u) + (int)((~umn) ^ 0x80000000u));
        }
        __syncthreads();
        shift = __float_as_int(red[31]);
    }

    // ---- setup: scores, flipped relevancy, gains ----
    if (tid < 256) {
        float sv = yp[b * N_DIM + tid];
        s[tid] = sv;
        int e = shift - ytr[b * N_DIM + tid];
        e = min(max(e, 0), 30);
        ei[tid] = e;
        gA[tid] = (float)((1u << e) - 1u);
        u[tid] = 1.0f;
    }
    __syncthreads();

    // ---- B_mat + IDCG rank: split across all 512 threads ----
    {
        const int row   = tid & 255;
        const int kbase = (tid >> 8) * 128;
        const float sr  = s[row];
        const int   er  = ei[row];
        float b0 = 0.f, b1 = 0.f;
        int pos = 0;
        #pragma unroll 8
        for (int k = 0; k < 128; k += 4) {
            float4 s4 = *(const float4*)(s + kbase + k);
            int4   e4 = *(const int4*)(ei + kbase + k);
            b0 += fabsf(sr - s4.x); b1 += fabsf(sr - s4.y);
            b0 += fabsf(sr - s4.z); b1 += fabsf(sr - s4.w);
            int kk = kbase + k;
            pos += ((e4.x > er) ? 1 : 0) + (((kk     < row) && (e4.x == er)) ? 1 : 0);
            pos += ((e4.y > er) ? 1 : 0) + (((kk + 1 < row) && (e4.y == er)) ? 1 : 0);
            pos += ((e4.z > er) ? 1 : 0) + (((kk + 2 < row) && (e4.z == er)) ? 1 : 0);
            pos += ((e4.w > er) ? 1 : 0) + (((kk + 3 < row) && (e4.w == er)) ? 1 : 0);
        }
        sp[tid] = b0 + b1;
        ((int*)sp)[512 + tid] = pos;
    }
    __syncthreads();
    float idcg = 0.f;
    if (tid < 256) {
        Bm[tid] = sp[tid] + sp[256 + tid];
        int pos = ((int*)sp)[512 + tid] + ((int*)sp)[768 + tid];
        float x = gA[tid] / log2f((float)(pos + 2));
        for (int o = 16; o; o >>= 1) x += __shfl_xor_sync(0xffffffffu, x, o);
        if (lane == 0) red[wid] = x;
    }
    __syncthreads();
    if (tid == 0) { for (int k = 0; k < 8; k++) idcg += red[k]; }

    // ==== P build (exp-free block scheme) ====
    if (tid < 256) {
        float r = __expf(-2.0f * s[tid]);
        float pk = 1.0f;
        pw[tid] = 1.0f;
        #pragma unroll
        for (int k = 1; k < 8; k++) { pk *= r; pw[k * 256 + tid] = pk; }
    }
    for (int m = wid; m < 32; m += 16) {
        float sc = (float)(255 - 16 * m);
        float lg[8];
        float mxl = -3.4e38f;
        #pragma unroll
        for (int c = 0; c < 8; c++) {
            int j = c * 32 + lane;
            lg[c] = fmaf(s[j], sc, -Bm[j]);
            mxl = fmaxf(mxl, lg[c]);
        }
        for (int o = 16; o; o >>= 1) mxl = fmaxf(mxl, __shfl_xor_sync(0xffffffffu, mxl, o));
        float* an = AN + m * 256;
        #pragma unroll
        for (int c = 0; c < 8; c++) an[c * 32 + lane] = __expf(lg[c] - mxl);
    }
    __syncthreads();

    // fill: warp per row; c<2 -> word 32c+lane, c>=2 -> word 32c+lane+16 (half1 @ +80)
    #pragma unroll 2
    for (int t = 0; t < 16; t++) {
        int i = wid + 16 * t;
        const float* an = AN + (i >> 3) * 256;
        const float* pk = pw + (i & 7) * 256;
        float f0[4], f1[4];
        float ssum = 0.f;
        #pragma unroll
        for (int c = 0; c < 4; c++) {
            float2 a2 = *(const float2*)(an + c * 64 + 2 * lane);
            float2 k2 = *(const float2*)(pk + c * 64 + 2 * lane);
            f0[c] = a2.x * k2.x;
            f1[c] = a2.y * k2.y;
            ssum += f0[c] + f1[c];
        }
        for (int o = 16; o; o >>= 1) ssum += __shfl_xor_sync(0xffffffffu, ssum, o);
        float inv = 1.0f / ssum;
        unsigned* row = Pw + (unsigned)i * RSW;
        #pragma unroll
        for (int c = 0; c < 4; c++) {
            __nv_bfloat162 pr = __floats2bfloat162_rn(f0[c] * inv, f1[c] * inv);
            row[c * 32 + lane + (c >= 2 ? 16 : 0)] = *(unsigned*)&pr;
        }
    }
    __syncthreads();

    // ---- Sinkhorn, fixed 50 iterations, 3 barriers/iter, 16-warp both passes ----
    const int cg = tid & 31;                          // col group: cols 8cg..8cg+7
    const int rg = tid >> 5;                          // row group: rows 16rg..16rg+15
    const unsigned* colp = Pw + (unsigned)(rg * 16) * RSW + 4u * (unsigned)cg
                              + (cg >= 16 ? 16u : 0u);
    const float* uo = u + rg * 16;
    const int rr = tid >> 1, hh = tid & 1;            // row-pass mapping (all 512)
    const unsigned* prow = Pw + (unsigned)rr * RSW + 80u * (unsigned)hh;
    const float* vbase = hh ? (vB + 128) : vA;

    for (int it = 0; it < ITERS; it++) {
        // column pass: 16 rows x 8 cols per thread (LDS.128 on P)
        float a0 = 0.f, a1 = 0.f, a2 = 0.f, a3 = 0.f;
        float a4 = 0.f, a5 = 0.f, a6 = 0.f, a7 = 0.f;
        #pragma unroll
        for (int q = 0; q < 4; q++) {
            float4 uu = *(const float4*)(uo + 4 * q);
            uint4 w0 = *(const uint4*)(colp + (4 * q + 0) * RSW);
            uint4 w1 = *(const uint4*)(colp + (4 * q + 1) * RSW);
            uint4 w2 = *(const uint4*)(colp + (4 * q + 2) * RSW);
            uint4 w3 = *(const uint4*)(colp + (4 * q + 3) * RSW);
            a0 = fmaf(bf_lo(w0.x), uu.x, a0); a1 = fmaf(bf_hi(w0.x), uu.x, a1);
            a2 = fmaf(bf_lo(w0.y), uu.x, a2); a3 = fmaf(bf_hi(w0.y), uu.x, a3);
            a4 = fmaf(bf_lo(w0.z), uu.x, a4); a5 = fmaf(bf_hi(w0.z), uu.x, a5);
            a6 = fmaf(bf_lo(w0.w), uu.x, a6); a7 = fmaf(bf_hi(w0.w), uu.x, a7);
            a0 = fmaf(bf_lo(w1.x), uu.y, a0); a1 = fmaf(bf_hi(w1.x), uu.y, a1);
            a2 = fmaf(bf_lo(w1.y), uu.y, a2); a3 = fmaf(bf_hi(w1.y), uu.y, a3);
            a4 = fmaf(bf_lo(w1.z), uu.y, a4); a5 = fmaf(bf_hi(w1.z), uu.y, a5);
            a6 = fmaf(bf_lo(w1.w), uu.y, a6); a7 = fmaf(bf_hi(w1.w), uu.y, a7);
            a0 = fmaf(bf_lo(w2.x), uu.z, a0); a1 = fmaf(bf_hi(w2.x), uu.z, a1);
            a2 = fmaf(bf_lo(w2.y), uu.z, a2); a3 = fmaf(bf_hi(w2.y), uu.z, a3);
            a4 = fmaf(bf_lo(w2.z), uu.z, a4); a5 = fmaf(bf_hi(w2.z), uu.z, a5);
            a6 = fmaf(bf_lo(w2.w), uu.z, a6); a7 = fmaf(bf_hi(w2.w), uu.z, a7);
            a0 = fmaf(bf_lo(w3.x), uu.w, a0); a1 = fmaf(bf_hi(w3.x), uu.w, a1);
            a2 = fmaf(bf_lo(w3.y), uu.w, a2); a3 = fmaf(bf_hi(w3.y), uu.w, a3);
            a4 = fmaf(bf_lo(w3.z), uu.w, a4); a5 = fmaf(bf_hi(w3.z), uu.w, a5);
            a6 = fmaf(bf_lo(w3.w), uu.w, a6); a7 = fmaf(bf_hi(w3.w), uu.w, a7);
        }
        float* spw = sp + rg * 256 + 8 * cg;
        *(float4*)(spw)     = make_float4(a0, a1, a2, a3);
        *(float4*)(spw + 4) = make_float4(a4, a5, a6, a7);
        __syncthreads();

        // v update (threads 0..255): sum 16 partials, dual store vA/vB
        if (tid < 256) {
            float s0 = 0.f, s1 = 0.f, s2 = 0.f, s3 = 0.f;
            #pragma unroll
            for (int g = 0; g < 16; g += 4) {
                s0 += sp[(g + 0) * 256 + tid];
                s1 += sp[(g + 1) * 256 + tid];
                s2 += sp[(g + 2) * 256 + tid];
                s3 += sp[(g + 3) * 256 + tid];
            }
            float vn = 1.0f / fmaxf((s0 + s1) + (s2 + s3), 1e-10f);
            vA[tid] = vn;
            vB[tid] = vn;
        }
        __syncthreads();

        // row pass: half-row per thread (all 512), scalar FMA, shfl-pair combine
        {
            float r0 = 0.f, r1 = 0.f, r2 = 0.f, r3 = 0.f;
            #pragma unroll
            for (int j4 = 0; j4 < 16; j4++) {
                float4 v0 = *(const float4*)(vbase + 8 * j4);
                float4 v1 = *(const float4*)(vbase + 8 * j4 + 4);
                uint4 pq = *(const uint4*)(prow + 4 * j4);
                r0 = fmaf(bf_lo(pq.x), v0.x, r0); r1 = fmaf(bf_hi(pq.x), v0.y, r1);
                r2 = fmaf(bf_lo(pq.y), v0.z, r2); r3 = fmaf(bf_hi(pq.y), v0.w, r3);
                r0 = fmaf(bf_lo(pq.z), v1.x, r0); r1 = fmaf(bf_hi(pq.z), v1.y, r1);
                r2 = fmaf(bf_lo(pq.w), v1.z, r2); r3 = fmaf(bf_hi(pq.w), v1.w, r3);
            }
            float dot = (r0 + r1) + (r2 + r3);
            dot += __shfl_xor_sync(0xffffffffu, dot, 1);
            if (hh == 0) u[rr] = 1.0f / fmaxf(dot, 1e-10f);
        }
        __syncthreads();
    }

    // ---- final: num = sum_i disc_i * u_i * (P[i] . (v*g)) ----
    if (tid < 256) {
        float wv = vA[tid] * gA[tid];
        vA[tid] = wv;
        vB[tid] = wv;
    }
    __syncthreads();
    {
        float r0 = 0.f, r1 = 0.f, r2 = 0.f, r3 = 0.f;
        #pragma unroll
        for (int j4 = 0; j4 < 16; j4++) {
            float4 v0 = *(const float4*)(vbase + 8 * j4);
            float4 v1 = *(const float4*)(vbase + 8 * j4 + 4);
            uint4 pq = *(const uint4*)(prow + 4 * j4);
            r0 = fmaf(bf_lo(pq.x), v0.x, r0); r1 = fmaf(bf_hi(pq.x), v0.y, r1);
            r2 = fmaf(bf_lo(pq.y), v0.z, r2); r3 = fmaf(bf_hi(pq.y), v0.w, r3);
            r0 = fmaf(bf_lo(pq.z), v1.x, r0); r1 = fmaf(bf_hi(pq.z), v1.y, r1);
            r2 = fmaf(bf_lo(pq.w), v1.z, r2); r3 = fmaf(bf_hi(pq.w), v1.w, r3);
        }
        float dot = (r0 + r1) + (r2 + r3);
        dot += __shfl_xor_sync(0xffffffffu, dot, 1);
        float val = (hh == 0) ? (u[rr] * dot / log2f((float)(rr + 2))) : 0.0f;
        for (int o = 16; o; o >>= 1) val += __shfl_xor_sync(0xffffffffu, val, o);
        if (lane == 0) red[wid] = val;
    }
    __syncthreads();

    // ---- fused global reduction (atomic ticket; last CTA writes output) ----
    if (tid == 0) {
        float num = 0.f;
        for (int k = 0; k < 16; k++) num += red[k];
        bool valid = (idcg != 0.0f);
        float nd = valid ? (num / (idcg + 1e-10f)) : 0.0f;
        atomicAdd(&g_sum, nd);
        atomicAdd(&g_cnt, valid ? 1 : 0);
        __threadfence();
        unsigned tk = atomicAdd(&g_tk, 1u);
        if (tk == (unsigned)(B_DIM - 1)) {
            float sm = atomicAdd(&g_sum, 0.0f);
            int   c  = atomicAdd(&g_cnt, 0);
            out[0] = (c > 0) ? (-(sm / (float)c)) : 0.0f;
            g_sum = 0.f;
            g_cnt = 0;
            __threadfence();
            g_tk = 0u;
        }
    }
}

// ------------------------------------------------------------------ launch ---
extern "C" void kernel_launch(void* const* d_in, const int* in_sizes, int n_in,
                              void* d_out, int out_size) {
    const float* yp  = (const float*)d_in[0];
    const int*   ytr = (const int*)d_in[1];
    float*       out = (float*)d_out;

    size_t smem = (size_t)SMEM_WORDS * 4;   // 216256 B
    cudaFuncSetAttribute(mega_kernel, cudaFuncAttributeMaxDynamicSharedMemorySize, (int)smem);
    mega_kernel<<<B_DIM, NTHR, smem>>>(yp, ytr, out);
}